// round 1
// baseline (speedup 1.0000x reference)
#include <cuda_runtime.h>

// Problem dims
#define MB 8
#define TT 4000
#define BBCH 128
#define HH 512
#define MT (MB*TT)      // 32000 rows
#define LP (TT+4)       // padded length for deform conv (pad_tot = 4)

// ---- scratch (device globals; no allocations allowed) ----
__device__ float g_h[MT * HH];     // prelu(x@W1^T), pre-norm   [M*T, H]
__device__ float g_p[MT * HH];     // prelu2(deform out), pre-norm
__device__ float g_off[MT * 3];    // offsets [M*T, 3]
__device__ float g_sum1[MB], g_sq1[MB], g_sum2[MB], g_sq2[MB];
__device__ float g_mu1[MB], g_iv1[MB], g_mu2[MB], g_iv2[MB];

// ---------------------------------------------------------------------------
__global__ void zero_stats_kernel() {
    int i = threadIdx.x;
    if (i < MB) { g_sum1[i] = 0.f; g_sq1[i] = 0.f; g_sum2[i] = 0.f; g_sq2[i] = 0.f; }
}

__global__ void finalize1_kernel() {
    int m = threadIdx.x;
    if (m < MB) {
        float n = (float)TT * (float)HH;
        float mu = g_sum1[m] / n;
        float var = g_sq1[m] / n - mu * mu;
        g_mu1[m] = mu;
        g_iv1[m] = 1.0f / sqrtf(var + 1e-8f);
    }
}

__global__ void finalize2_kernel() {
    int m = threadIdx.x;
    if (m < MB) {
        float n = (float)TT * (float)HH;
        float mu = g_sum2[m] / n;
        float var = g_sq2[m] / n - mu * mu;
        g_mu2[m] = mu;
        g_iv2[m] = 1.0f / sqrtf(var + 1e-8f);
    }
}

// ---------------------------------------------------------------------------
// GEMM1: h[row, n] = prelu( sum_k x[row,k] * W1[n,k] ), row in [0,32000), n in [0,512), k in [0,128)
// Also accumulates per-sample sum / sumsq of the prelu'ed values (gLN stats).
// 64x64 tile, 16x16 threads, 4x4 microtile, BK=16.
__global__ void gemm1_kernel(const float* __restrict__ A,   // x [32000,128]
                             const float* __restrict__ W,   // conv1_w [512,128]
                             const float* __restrict__ prelu_a) {
    __shared__ float As[16][65];
    __shared__ float Bs[16][65];
    __shared__ float red[256];
    const int rowTile = blockIdx.x * 64;
    const int colTile = blockIdx.y * 64;
    const int tid = threadIdx.y * 16 + threadIdx.x;
    float acc[4][4] = {};

    for (int k0 = 0; k0 < BBCH; k0 += 16) {
#pragma unroll
        for (int i = 0; i < 4; i++) {
            int e = tid + i * 256;           // 0..1023
            int r = e >> 4, c = e & 15;
            As[c][r] = A[(size_t)(rowTile + r) * BBCH + k0 + c];
            Bs[c][r] = W[(size_t)(colTile + r) * BBCH + k0 + c];
        }
        __syncthreads();
#pragma unroll
        for (int kk = 0; kk < 16; kk++) {
            float ra[4], rb[4];
#pragma unroll
            for (int i = 0; i < 4; i++) ra[i] = As[kk][threadIdx.y * 4 + i];
#pragma unroll
            for (int j = 0; j < 4; j++) rb[j] = Bs[kk][threadIdx.x * 4 + j];
#pragma unroll
            for (int i = 0; i < 4; i++)
#pragma unroll
                for (int j = 0; j < 4; j++) acc[i][j] += ra[i] * rb[j];
        }
        __syncthreads();
    }

    const float a = prelu_a[0];
    const int m0 = rowTile / TT;
    const int m1 = (rowTile + 63) / TT;
    float s[2] = {0.f, 0.f}, q[2] = {0.f, 0.f};
#pragma unroll
    for (int i = 0; i < 4; i++) {
        int row = rowTile + threadIdx.y * 4 + i;
        int bin = (row / TT) - m0;   // 0 or 1
#pragma unroll
        for (int j = 0; j < 4; j++) {
            float v = acc[i][j];
            v = v >= 0.f ? v : a * v;
            g_h[(size_t)row * HH + colTile + threadIdx.x * 4 + j] = v;
            s[bin] += v;
            q[bin] += v * v;
        }
    }
    int nb = (m1 > m0) ? 2 : 1;
    for (int b = 0; b < nb; b++) {
        red[tid] = s[b]; __syncthreads();
        for (int off = 128; off > 0; off >>= 1) {
            if (tid < off) red[tid] += red[tid + off];
            __syncthreads();
        }
        if (tid == 0) atomicAdd(&g_sum1[m0 + b], red[0]);
        __syncthreads();
        red[tid] = q[b]; __syncthreads();
        for (int off = 128; off > 0; off >>= 1) {
            if (tid < off) red[tid] += red[tid + off];
            __syncthreads();
        }
        if (tid == 0) atomicAdd(&g_sq1[m0 + b], red[0]);
        __syncthreads();
    }
}

// ---------------------------------------------------------------------------
// Offset branch: per (m,t): depthwise K=3 dilation-1 reflect conv on normalized h,
// PReLU, then [3,H] pointwise, PReLU -> g_off[m*T+t, 0..2]
__global__ void offsets_kernel(const float* __restrict__ odww,  // off_dw_w [512,3]
                               const float* __restrict__ odc_a,
                               const float* __restrict__ opww,  // off_pw_w [3,512]
                               const float* __restrict__ opc_a,
                               const float* __restrict__ gam,   // norm1_g
                               const float* __restrict__ bet) { // norm1_b
    const int mt = blockIdx.x;
    const int m = mt / TT;
    const int t = mt - m * TT;
    const int tm1 = (t == 0) ? 1 : t - 1;          // reflect
    const int tp1 = (t == TT - 1) ? TT - 2 : t + 1;
    const float* base = g_h + (size_t)m * TT * HH;
    const float* r0 = base + (size_t)tm1 * HH;
    const float* r1 = base + (size_t)t * HH;
    const float* r2 = base + (size_t)tp1 * HH;
    const float mu = g_mu1[m], iv = g_iv1[m];
    const float aodc = odc_a[0];

    float s0 = 0.f, s1 = 0.f, s2 = 0.f;
    for (int c = threadIdx.x; c < HH; c += 128) {
        float gc = gam[c] * iv;
        float bc = bet[c] - gc * mu;   // hn = gc*h + bc
        float x0 = gc * r0[c] + bc;
        float x1 = gc * r1[c] + bc;
        float x2 = gc * r2[c] + bc;
        float od = odww[c * 3] * x0 + odww[c * 3 + 1] * x1 + odww[c * 3 + 2] * x2;
        od = od >= 0.f ? od : aodc * od;
        s0 += opww[c] * od;
        s1 += opww[HH + c] * od;
        s2 += opww[2 * HH + c] * od;
    }
#pragma unroll
    for (int o = 16; o > 0; o >>= 1) {
        s0 += __shfl_down_sync(0xffffffffu, s0, o);
        s1 += __shfl_down_sync(0xffffffffu, s1, o);
        s2 += __shfl_down_sync(0xffffffffu, s2, o);
    }
    __shared__ float sh[4][3];
    int w = threadIdx.x >> 5;
    if ((threadIdx.x & 31) == 0) { sh[w][0] = s0; sh[w][1] = s1; sh[w][2] = s2; }
    __syncthreads();
    if (threadIdx.x == 0) {
        float aopc = opc_a[0];
        float v0 = sh[0][0] + sh[1][0] + sh[2][0] + sh[3][0];
        float v1 = sh[0][1] + sh[1][1] + sh[2][1] + sh[3][1];
        float v2 = sh[0][2] + sh[1][2] + sh[2][2] + sh[3][2];
        g_off[mt * 3 + 0] = v0 >= 0.f ? v0 : aopc * v0;
        g_off[mt * 3 + 1] = v1 >= 0.f ? v1 : aopc * v1;
        g_off[mt * 3 + 2] = v2 >= 0.f ? v2 : aopc * v2;
    }
}

// ---------------------------------------------------------------------------
// Reflect-map padded index (xp index j) back to source time: i = j-2 reflected.
__device__ __forceinline__ int mapref(int i) {
    if (i < 0) i = -i;
    if (i >= TT) i = 2 * TT - 2 - i;
    return i;
}

// Deformable depthwise conv + bias + PReLU2, fused gLN2 stats.
__global__ void deform_kernel(const float* __restrict__ dww,  // dw_w [512,3]
                              const float* __restrict__ dwb,  // dw_b [512]
                              const float* __restrict__ a2p,
                              const float* __restrict__ gam,  // norm1_g
                              const float* __restrict__ bet) {
    const int mt = blockIdx.x;
    const int m = mt / TT;
    const int t = mt - m * TT;
    __shared__ float sg0[3], sg1[3];
    __shared__ int sr0[3], sr1[3];
    __shared__ float red[128];

    if (threadIdx.x < 3) {
        int k = threadIdx.x;
        float tpos = (float)t + 2.0f * (float)k + g_off[mt * 3 + k];
        tpos = fminf(fmaxf(tpos, (float)t), (float)(t + 4));  // clip to receptive field
        int U = (int)floorf(tpos);
        U = min(max(U, 0), LP - 2);
        float Uf = (float)U;
        sg0[k] = fmaxf(1.0f - fabsf(Uf - tpos), 0.0f);
        sg1[k] = fmaxf(1.0f - fabsf(Uf + 1.0f - tpos), 0.0f);
        sr0[k] = mapref(U - 2);      // xp[U]   -> source time
        sr1[k] = mapref(U - 1);      // xp[U+1] -> source time
    }
    __syncthreads();

    const float* base = g_h + (size_t)m * TT * HH;
    const float mu = g_mu1[m], iv = g_iv1[m];
    const float a2 = a2p[0];
    float lsum = 0.f, lsq = 0.f;
    for (int h = threadIdx.x; h < HH; h += 128) {
        float gc = gam[h] * iv;
        float bc = bet[h] - gc * mu;
        float y = dwb[h];
#pragma unroll
        for (int k = 0; k < 3; k++) {
            float v0 = gc * base[(size_t)sr0[k] * HH + h] + bc;
            float v1 = gc * base[(size_t)sr1[k] * HH + h] + bc;
            y += dww[h * 3 + k] * (sg0[k] * v0 + sg1[k] * v1);
        }
        float p = y >= 0.f ? y : a2 * y;
        g_p[(size_t)mt * HH + h] = p;
        lsum += p; lsq += p * p;
    }
    red[threadIdx.x] = lsum; __syncthreads();
    for (int o = 64; o > 0; o >>= 1) {
        if (threadIdx.x < o) red[threadIdx.x] += red[threadIdx.x + o];
        __syncthreads();
    }
    if (threadIdx.x == 0) atomicAdd(&g_sum2[m], red[0]);
    __syncthreads();
    red[threadIdx.x] = lsq; __syncthreads();
    for (int o = 64; o > 0; o >>= 1) {
        if (threadIdx.x < o) red[threadIdx.x] += red[threadIdx.x + o];
        __syncthreads();
    }
    if (threadIdx.x == 0) atomicAdd(&g_sq2[m], red[0]);
}

// ---------------------------------------------------------------------------
// GEMM2: out[row,b] = x[row,b] + sum_h W2[b,h] * ( gln2 applied to g_p[row,h] )
// gLN folded into A-tile load. 64x64 tile (grid.y = 2), BK=16.
__global__ void gemm2_kernel(const float* __restrict__ W,    // pw_w [128,512]
                             const float* __restrict__ gam,  // norm2_g
                             const float* __restrict__ bet,  // norm2_b
                             const float* __restrict__ X,    // residual x [32000,128]
                             float* __restrict__ out) {
    __shared__ float As[16][65];
    __shared__ float Bs[16][65];
    const int rowTile = blockIdx.x * 64;
    const int colTile = blockIdx.y * 64;
    const int tid = threadIdx.y * 16 + threadIdx.x;
    float acc[4][4] = {};

    for (int k0 = 0; k0 < HH; k0 += 16) {
#pragma unroll
        for (int i = 0; i < 4; i++) {
            int e = tid + i * 256;
            int r = e >> 4, c = e & 15;
            int row = rowTile + r;
            int mm = row / TT;
            int k = k0 + c;
            float v = g_p[(size_t)row * HH + k];
            float gc = gam[k] * g_iv2[mm];
            As[c][r] = gc * v + (bet[k] - gc * g_mu2[mm]);
            Bs[c][r] = W[(size_t)(colTile + r) * HH + k];
        }
        __syncthreads();
#pragma unroll
        for (int kk = 0; kk < 16; kk++) {
            float ra[4], rb[4];
#pragma unroll
            for (int i = 0; i < 4; i++) ra[i] = As[kk][threadIdx.y * 4 + i];
#pragma unroll
            for (int j = 0; j < 4; j++) rb[j] = Bs[kk][threadIdx.x * 4 + j];
#pragma unroll
            for (int i = 0; i < 4; i++)
#pragma unroll
                for (int j = 0; j < 4; j++) acc[i][j] += ra[i] * rb[j];
        }
        __syncthreads();
    }
#pragma unroll
    for (int i = 0; i < 4; i++) {
        int row = rowTile + threadIdx.y * 4 + i;
#pragma unroll
        for (int j = 0; j < 4; j++) {
            int col = colTile + threadIdx.x * 4 + j;
            out[(size_t)row * BBCH + col] = acc[i][j] + X[(size_t)row * BBCH + col];
        }
    }
}

// ---------------------------------------------------------------------------
extern "C" void kernel_launch(void* const* d_in, const int* in_sizes, int n_in,
                              void* d_out, int out_size) {
    (void)in_sizes; (void)n_in; (void)out_size;
    const float* x        = (const float*)d_in[0];
    const float* conv1_w  = (const float*)d_in[1];
    const float* prelu1_a = (const float*)d_in[2];
    const float* norm1_g  = (const float*)d_in[3];
    const float* norm1_b  = (const float*)d_in[4];
    const float* off_dw_w = (const float*)d_in[5];
    const float* odc_a    = (const float*)d_in[6];
    const float* off_pw_w = (const float*)d_in[7];
    const float* opc_a    = (const float*)d_in[8];
    const float* dw_w     = (const float*)d_in[9];
    const float* dw_b     = (const float*)d_in[10];
    const float* prelu2_a = (const float*)d_in[11];
    const float* norm2_g  = (const float*)d_in[12];
    const float* norm2_b  = (const float*)d_in[13];
    const float* pw_w     = (const float*)d_in[14];
    float* out = (float*)d_out;

    zero_stats_kernel<<<1, 32>>>();
    gemm1_kernel<<<dim3(MT / 64, HH / 64), dim3(16, 16)>>>(x, conv1_w, prelu1_a);
    finalize1_kernel<<<1, MB>>>();
    offsets_kernel<<<MT, 128>>>(off_dw_w, odc_a, off_pw_w, opc_a, norm1_g, norm1_b);
    deform_kernel<<<MT, 128>>>(dw_w, dw_b, prelu2_a, norm1_g, norm1_b);
    finalize2_kernel<<<1, MB>>>();
    gemm2_kernel<<<dim3(MT / 64, BBCH / 64), dim3(16, 16)>>>(pw_w, norm2_g, norm2_b, x, out);
}